// round 13
// baseline (speedup 1.0000x reference)
#include <cuda_runtime.h>
#include <cuda_bf16.h>
#include <cstdint>
#include <math.h>

#define BQ 8
#define LQ 1024
#define DQ 768
#define NST 16
#define RQ 48
#define MROWS (BQ*LQ)   // 8192
#define NCH 32
#define CS  (LQ/NCH)    // 32

// ---------------- scratch (device globals) ------------------------------------
__device__ __nv_bfloat16  g_hidb[MROWS*DQ];
__device__ __nv_bfloat16  g_xinb[MROWS*DQ];       // in_proj x-half, bf16
__device__ __nv_bfloat16  g_zb  [MROWS*DQ];       // in_proj z-half, bf16
__device__ __nv_bfloat16  g_xcb [MROWS*DQ];
__device__ __nv_bfloat16  g_tmpb[MROWS*64];       // dt_raw padded to 64, bf16
__device__ float          g_dt  [MROWS*DQ];
__device__ float          g_bc  [MROWS*32];
__device__ __nv_bfloat16  g_yb  [MROWS*DQ];
__device__ __nv_bfloat16  g_wib [2*DQ*DQ];
__device__ __nv_bfloat16  g_wob [DQ*DQ];
__device__ __nv_bfloat16  g_xpwb[80*DQ];
__device__ __nv_bfloat16  g_dtwb[DQ*64];
__device__ float          g_pos [LQ*DQ];

// ---------------- asm helpers -------------------------------------------------
__device__ __forceinline__ uint32_t smem_u32(const void* p) {
    uint32_t a;
    asm("{ .reg .u64 t; cvta.to.shared.u64 t, %1; cvt.u32.u64 %0, t; }" : "=r"(a) : "l"(p));
    return a;
}
#define GD_LAUNCH() asm volatile("griddepcontrol.launch_dependents;")
#define GD_WAIT()   asm volatile("griddepcontrol.wait;" ::: "memory")
#define CPASYNC16(d, s) \
    asm volatile("cp.async.cg.shared.global [%0], [%1], 16;" :: "r"(d), "l"(s))
#define CP_COMMIT()  asm volatile("cp.async.commit_group;")
#define CP_WAIT1()   asm volatile("cp.async.wait_group 1;")
#define CP_WAIT0()   asm volatile("cp.async.wait_group 0;")
#define LDSM4(r0, r1, r2, r3, a) \
    asm volatile("ldmatrix.sync.aligned.m8n8.x4.shared.b16 {%0,%1,%2,%3}, [%4];" \
        : "=r"(r0), "=r"(r1), "=r"(r2), "=r"(r3) : "r"(a))
#define MMA16816(d, a, b) \
    asm volatile("mma.sync.aligned.m16n8k16.row.col.f32.bf16.bf16.f32 " \
        "{%0,%1,%2,%3}, {%4,%5,%6,%7}, {%8,%9}, {%0,%1,%2,%3};" \
        : "+f"((d)[0]), "+f"((d)[1]), "+f"((d)[2]), "+f"((d)[3]) \
        : "r"((a)[0]), "r"((a)[1]), "r"((a)[2]), "r"((a)[3]), \
          "r"((b)[0]), "r"((b)[1]))

// ---- packed f32x2 ----
typedef unsigned long long u64t;
#define F2_FMA(d, a, b, c) asm("fma.rn.f32x2 %0, %1, %2, %3;" : "=l"(d) : "l"(a), "l"(b), "l"(c))
#define F2_MUL(d, a, b)    asm("mul.rn.f32x2 %0, %1, %2;"     : "=l"(d) : "l"(a), "l"(b))
#define F2_ADD(d, a, b)    asm("add.rn.f32x2 %0, %1, %2;"     : "=l"(d) : "l"(a), "l"(b))
#define PK2(d, lo, hi)     asm("mov.b64 %0, {%1, %2};" : "=l"(d) : "r"(lo), "r"(hi))
#define UPK2(lo, hi, s)    asm("mov.b64 {%0, %1}, %2;" : "=r"(lo), "=r"(hi) : "l"(s))

__device__ __forceinline__ u64t bcast2(float x) {
    uint32_t b = __float_as_uint(x);
    u64t d; PK2(d, b, b); return d;
}
__device__ __forceinline__ u64t exp2x2(u64t t2, u64t MAG, u64t NMAG, u64t NEG1,
                                       u64t C4, u64t C3, u64t C2, u64t C1, u64t ONE) {
    u64t z2; F2_ADD(z2, t2, MAG);
    uint32_t zl, zh; UPK2(zl, zh, z2);
    u64t zr2; F2_ADD(zr2, z2, NMAG);
    u64t f2;  F2_FMA(f2, zr2, NEG1, t2);
    u64t p2 = C4;
    F2_FMA(p2, p2, f2, C3);
    F2_FMA(p2, p2, f2, C2);
    F2_FMA(p2, p2, f2, C1);
    F2_FMA(p2, p2, f2, ONE);
    uint32_t pl, ph; UPK2(pl, ph, p2);
    pl += (zl - 0x4B400000u) << 23;
    ph += (zh - 0x4B400000u) << 23;
    u64t r; PK2(r, pl, ph); return r;
}
#define EXP2_CONSTS                                   \
    const u64t MAG  = bcast2(12582912.0f);            \
    const u64t NMAG = bcast2(-12582912.0f);           \
    const u64t NEG1 = bcast2(-1.0f);                  \
    const u64t PC4  = bcast2(9.6181291e-3f);          \
    const u64t PC3  = bcast2(5.5504110e-2f);          \
    const u64t PC2  = bcast2(2.4022651e-1f);          \
    const u64t PC1  = bcast2(6.9314718e-1f);          \
    const u64t ONE2 = bcast2(1.0f);

// ---------------- HMMA GEMM ----------------------------------------------------
// MODE 0: in_proj split: c<768 -> g_xinb bf16; c>=768 -> g_zb bf16
// MODE 1: C = softplus(acc + bias)
// MODE 2: C = acc + bias + x + pos-table
// MODE 3: x_proj split: c<48 -> tmpb; 48<=c<64 -> tmpb=0 & bc; 64<=c<80 -> bc
#define SROW 72
#define STGB (128*SROW*2)
#define STAGEB (2*STGB)
#define NSTAGE 3

template<int MODE, int KT>
__global__ void __launch_bounds__(256, 2) mma_gemm(
    const __nv_bfloat16* __restrict__ A, const __nv_bfloat16* __restrict__ W,
    const float* __restrict__ bias, const float* __restrict__ resid,
    float* __restrict__ C, float* __restrict__ bc, int N, int Wrows)
{
    extern __shared__ __align__(16) char dyn[];
    const uint32_t smemBase = smem_u32(dyn);

    GD_LAUNCH();

    const int tid  = threadIdx.x;
    const int lane = tid & 31;
    const int w    = tid >> 5;
    const int wm   = (w >> 2) * 64;
    const int wn   = (w & 3) * 32;
    const int gid  = lane >> 2;
    const int tig  = lane & 3;
    const int m0   = blockIdx.y * 128;
    const int n0   = blockIdx.x * 128;

    const uint32_t aOff = (uint32_t)(wm + (lane & 15)) * 144 + ((lane >> 4) << 4);
    const uint32_t bOff = (uint32_t)(wn + ((lane >> 4) << 3) + (lane & 7)) * 144
                        + (((lane >> 3) & 1) << 4) + STGB;

    auto issue = [&](int kt, int stage) {
        uint32_t dA = smemBase + stage * STAGEB;
        uint32_t dB = dA + STGB;
        int koff = kt * 64;
        #pragma unroll
        for (int i = 0; i < 4; i++) {
            int c = tid + i * 256;
            int row = c >> 3, q = c & 7;
            CPASYNC16(dA + row * 144 + q * 16,
                      A + (size_t)(m0 + row) * KT + koff + q * 8);
            int gn = n0 + row;
            int gnc = gn < Wrows ? gn : 0;
            CPASYNC16(dB + row * 144 + q * 16,
                      W + (size_t)gnc * KT + koff + q * 8);
        }
        CP_COMMIT();
    };

    float acc[4][4][4];
    #pragma unroll
    for (int mt = 0; mt < 4; mt++)
        #pragma unroll
        for (int nt = 0; nt < 4; nt++)
            #pragma unroll
            for (int i = 0; i < 4; i++) acc[mt][nt][i] = 0.f;

    GD_WAIT();   // A and W written by predecessors

    constexpr int nk = KT / 64;
    issue(0, 0);
    if constexpr (nk > 1) issue(1, 1);

    #pragma unroll
    for (int kt = 0; kt < nk; kt++) {
        if (kt == nk - 1) CP_WAIT0();
        else              CP_WAIT1();
        __syncthreads();
        int st = kt % NSTAGE;
        uint32_t aB = smemBase + st * STAGEB + aOff;
        uint32_t bB = smemBase + st * STAGEB + bOff;
        #pragma unroll
        for (int ks = 0; ks < 4; ks++) {
            uint32_t ko = ks * 32;
            uint32_t af[4][4], bf[4][2];
            #pragma unroll
            for (int mt = 0; mt < 4; mt++)
                LDSM4(af[mt][0], af[mt][1], af[mt][2], af[mt][3],
                      aB + mt * (16 * 144) + ko);
            #pragma unroll
            for (int p = 0; p < 2; p++)
                LDSM4(bf[2*p][0], bf[2*p][1], bf[2*p+1][0], bf[2*p+1][1],
                      bB + p * (16 * 144) + ko);
            #pragma unroll
            for (int mt = 0; mt < 4; mt++)
                #pragma unroll
                for (int nt = 0; nt < 4; nt++)
                    MMA16816(acc[mt][nt], af[mt], bf[nt]);
        }
        if (kt + 2 < nk) issue(kt + 2, (kt + 2) % NSTAGE);
    }

    #pragma unroll
    for (int mt = 0; mt < 4; mt++) {
        int r0 = m0 + wm + mt * 16 + gid;
        #pragma unroll
        for (int nt = 0; nt < 4; nt++) {
            int c0 = n0 + wn + nt * 8 + tig * 2;
            if (MODE == 0) {
                float bv0 = bias[c0], bv1 = bias[c0 + 1];
                #pragma unroll
                for (int h = 0; h < 2; h++) {
                    int r = r0 + h * 8;
                    float v0 = acc[mt][nt][h * 2 + 0] + bv0;
                    float v1 = acc[mt][nt][h * 2 + 1] + bv1;
                    __nv_bfloat162 pv(__float2bfloat16(v0), __float2bfloat16(v1));
                    if (c0 < DQ)
                        *(__nv_bfloat162*)(g_xinb + (size_t)r * DQ + c0) = pv;
                    else
                        *(__nv_bfloat162*)(g_zb + (size_t)r * DQ + (c0 - DQ)) = pv;
                }
            } else if (MODE == 1) {
                #pragma unroll
                for (int h = 0; h < 2; h++) {
                    int r = r0 + h * 8;
                    #pragma unroll
                    for (int j = 0; j < 2; j++) {
                        int c = c0 + j;
                        float t = acc[mt][nt][h * 2 + j] + bias[c];
                        C[(size_t)r * DQ + c] =
                            fmaxf(t, 0.f) + log1pf(expf(-fabsf(t)));
                    }
                }
            } else if (MODE == 2) {
                #pragma unroll
                for (int h = 0; h < 2; h++) {
                    int r = r0 + h * 8;
                    int l = r & (LQ - 1);
                    float2 ps = *(const float2*)(g_pos + (size_t)l * DQ + c0);
                    float2 xr = *(const float2*)(resid + (size_t)r * DQ + c0);
                    float2 out;
                    out.x = acc[mt][nt][h * 2 + 0] + bias[c0]     + xr.x + ps.x;
                    out.y = acc[mt][nt][h * 2 + 1] + bias[c0 + 1] + xr.y + ps.y;
                    *(float2*)(C + (size_t)r * DQ + c0) = out;
                }
            } else {   // MODE 3
                #pragma unroll
                for (int h = 0; h < 2; h++) {
                    int r = r0 + h * 8;
                    #pragma unroll
                    for (int j = 0; j < 2; j++) {
                        int c = c0 + j;
                        float v = acc[mt][nt][h * 2 + j];
                        if (c < 48) {
                            g_tmpb[(size_t)r * 64 + c] = __float2bfloat16(v);
                        } else if (c < 64) {
                            g_tmpb[(size_t)r * 64 + c] = __float2bfloat16(0.f);
                            bc[(size_t)r * 32 + (c - 48)] = v;
                        } else if (c < 80) {
                            bc[(size_t)r * 32 + (c - 48)] = v;
                        }
                    }
                }
            }
        }
    }
}

// ---------------- merged prep: weights + dtw pad + pos table -------------------
__global__ void k_prep(const float* __restrict__ wi, const float* __restrict__ wo,
                       const float* __restrict__ xpw, const float* __restrict__ dtw,
                       __nv_bfloat16* __restrict__ di, __nv_bfloat16* __restrict__ dob,
                       __nv_bfloat16* __restrict__ xpb, __nv_bfloat16* __restrict__ dtb)
{
    GD_LAUNCH();
    const int n1q = (2*DQ*DQ) / 4;
    const int n2q = n1q + (DQ*DQ) / 4;
    const int n3q = n2q + (80*DQ) / 4;
    const int ndt = DQ * 64;
    const int npos = LQ * DQ;
    for (int i = blockIdx.x * blockDim.x + threadIdx.x; i < n3q + ndt + npos;
         i += gridDim.x * blockDim.x) {
        if (i < n3q) {
            const float* s; __nv_bfloat16* d; int q;
            if (i < n1q)      { s = wi;  d = di;  q = i; }
            else if (i < n2q) { s = wo;  d = dob; q = i - n1q; }
            else              { s = xpw; d = xpb; q = i - n2q; }
            float4 v = *(const float4*)(s + (size_t)q * 4);
            __nv_bfloat162* o = (__nv_bfloat162*)(d + (size_t)q * 4);
            o[0] = __nv_bfloat162(__float2bfloat16(v.x), __float2bfloat16(v.y));
            o[1] = __nv_bfloat162(__float2bfloat16(v.z), __float2bfloat16(v.w));
        } else if (i < n3q + ndt) {
            int idx = i - n3q;
            int n = idx >> 6, r = idx & 63;
            dtb[idx] = __float2bfloat16(r < RQ ? dtw[n * RQ + r] : 0.f);
        } else {
            int idx = i - n3q - ndt;
            int l = idx / DQ, c = idx % DQ;
            int chan = c >> 8, f = c & 255;
            float ch = (float)(l >> 6) * (1.0f/15.0f);
            float cw = (float)((l >> 2) & 15) * (1.0f/15.0f);
            float cd = (float)(l & 3) * (1.0f/3.0f);
            float cv = (chan == 0) ? ch : (chan == 1) ? cw : cd;
            float om  = exp2f(-(float)(f & 127) * (13.287712379549449f/128.0f));
            float arg = cv * om;
            g_pos[idx] = (f & 128) ? __cosf(arg) : __sinf(arg);
        }
    }
}

// ---------------- pos(table) + residual + rmsnorm ------------------------------
__global__ void __launch_bounds__(256) k_prenorm(const float* __restrict__ x,
                                                 const float* __restrict__ norm_w)
{
    GD_LAUNCH();
    int row = blockIdx.x;
    int l   = row & (LQ - 1);
    const float* xr = x + (size_t)row * DQ;
    const float* pr = g_pos + (size_t)l * DQ;

    // x is a harness input: load before the PDL wait
    float xv[3];
    #pragma unroll
    for (int i = 0; i < 3; i++) xv[i] = xr[threadIdx.x + i * 256];

    GD_WAIT();   // pos table from k_prep

    float vals[3];
    float ss = 0.f;
    #pragma unroll
    for (int i = 0; i < 3; i++) {
        int j = threadIdx.x + i * 256;
        float v = xv[i] + pr[j];
        vals[i] = v;
        ss += v * v;
    }
    #pragma unroll
    for (int o = 16; o > 0; o >>= 1) ss += __shfl_xor_sync(0xffffffffu, ss, o);
    __shared__ float part[8];
    if ((threadIdx.x & 31) == 0) part[threadIdx.x >> 5] = ss;
    __syncthreads();
    float tot = part[0] + part[1] + part[2] + part[3]
              + part[4] + part[5] + part[6] + part[7];
    float scale = rsqrtf(tot * (1.0f/(float)DQ) + 1e-5f);

    __nv_bfloat16* hr = g_hidb + (size_t)row * DQ;
    #pragma unroll
    for (int i = 0; i < 3; i++) {
        int j = threadIdx.x + i * 256;
        hr[j] = __float2bfloat16(vals[i] * scale * norm_w[j]);
    }
}

// ---------------- causal conv (K=4, bf16 in) + silu ----------------------------
__device__ __forceinline__ float4 ld_bf4(const __nv_bfloat16* p) {
    uint2 u = *(const uint2*)p;
    __nv_bfloat162 a = *(const __nv_bfloat162*)&u.x;
    __nv_bfloat162 b = *(const __nv_bfloat162*)&u.y;
    return make_float4(__bfloat162float(a.x), __bfloat162float(a.y),
                       __bfloat162float(b.x), __bfloat162float(b.y));
}

__global__ void __launch_bounds__(256) k_conv(const float* __restrict__ conv_w,
                                              const float* __restrict__ conv_b)
{
    GD_LAUNCH();
    const int ND4 = DQ / 4;
    int idx = blockIdx.x * 256 + threadIdx.x;
    if (idx >= (MROWS/4) * ND4) { GD_WAIT(); return; }
    int d4 = (idx % ND4) * 4;
    int m0 = (idx / ND4) * 4;
    int l0 = m0 & (LQ - 1);

    // harness inputs: load pre-wait
    float4 w0 = *(const float4*)(conv_w + (d4+0)*4);
    float4 w1 = *(const float4*)(conv_w + (d4+1)*4);
    float4 w2 = *(const float4*)(conv_w + (d4+2)*4);
    float4 w3 = *(const float4*)(conv_w + (d4+3)*4);
    float4 bv = *(const float4*)(conv_b + d4);

    GD_WAIT();   // g_xinb from in_proj

    float4 xin[7];
    #pragma unroll
    for (int j = 0; j < 7; j++) {
        int lj = l0 - 3 + j;
        xin[j] = (lj >= 0)
               ? ld_bf4(g_xinb + (size_t)(m0 - 3 + j) * DQ + d4)
               : make_float4(0.f, 0.f, 0.f, 0.f);
    }
    #pragma unroll
    for (int t = 0; t < 4; t++) {
        float4 acc = bv;
        #pragma unroll
        for (int k = 0; k < 4; k++) {
            float4 xv = xin[t + k];
            acc.x = fmaf(xv.x, ((const float*)&w0)[k], acc.x);
            acc.y = fmaf(xv.y, ((const float*)&w1)[k], acc.y);
            acc.z = fmaf(xv.z, ((const float*)&w2)[k], acc.z);
            acc.w = fmaf(xv.w, ((const float*)&w3)[k], acc.w);
        }
        float4 s;
        s.x = acc.x / (1.f + __expf(-acc.x));
        s.y = acc.y / (1.f + __expf(-acc.y));
        s.z = acc.z / (1.f + __expf(-acc.z));
        s.w = acc.w / (1.f + __expf(-acc.w));
        __nv_bfloat162* o = (__nv_bfloat162*)(g_xcb + (size_t)(m0 + t) * DQ + d4);
        o[0] = __nv_bfloat162(__float2bfloat16(s.x), __float2bfloat16(s.y));
        o[1] = __nv_bfloat162(__float2bfloat16(s.z), __float2bfloat16(s.w));
    }
}

// ---------------- fused chunked scan -------------------------------------------
__global__ void __launch_bounds__(256) k_scan(const float* __restrict__ A_log,
                                              const float* __restrict__ D_param)
{
    __shared__ float sP[NCH][8][17];
    __shared__ float sS[NCH][8][17];

    GD_LAUNCH();

    int b  = blockIdx.x / (DQ/8);
    int d0 = (blockIdx.x % (DQ/8)) * 8;
    int t  = threadIdx.x;
    int ch = t >> 3;
    int dl = t & 7;
    int d  = d0 + dl;

    EXP2_CONSTS;
    // harness inputs: heavy MUFU setup runs pre-wait (overlaps predecessor tail)
    u64t Av2[8];
    #pragma unroll
    for (int i = 0; i < 8; i++) {
        float a0 = -expf(A_log[d * NST + 2*i])     * 1.4426950408889634f;
        float a1 = -expf(A_log[d * NST + 2*i + 1]) * 1.4426950408889634f;
        PK2(Av2[i], __float_as_uint(a0), __float_as_uint(a1));
    }
    float Dv = D_param[d];

    GD_WAIT();   // g_dt, g_xcb, g_bc, g_zb from predecessors

    u64t h2[8], P2[8];
    const u64t Z = bcast2(0.0f);
    #pragma unroll
    for (int i = 0; i < 8; i++) { h2[i] = Z; P2[i] = ONE2; }

    size_t mbase = (size_t)b * LQ + ch * CS;
    for (int s = 0; s < CS; s++) {
        size_t m = mbase + s;
        float dt = g_dt[m * DQ + d];
        float xc = __bfloat162float(g_xcb[m * DQ + d]);
        u64t dt2 = bcast2(dt);
        u64t u2  = bcast2(dt * xc);
        const u64t* bp = (const u64t*)(g_bc + m * 32);
        #pragma unroll
        for (int i = 0; i < 8; i++) {
            u64t t2; F2_MUL(t2, dt2, Av2[i]);
            u64t dA2 = exp2x2(t2, MAG, NMAG, NEG1, PC4, PC3, PC2, PC1, ONE2);
            u64t uB2; F2_MUL(uB2, u2, bp[i]);
            F2_FMA(h2[i], dA2, h2[i], uB2);
            F2_MUL(P2[i], P2[i], dA2);
        }
    }
    #pragma unroll
    for (int i = 0; i < 8; i++) {
        uint32_t lo, hi;
        UPK2(lo, hi, h2[i]); sS[ch][dl][2*i] = __uint_as_float(lo); sS[ch][dl][2*i+1] = __uint_as_float(hi);
        UPK2(lo, hi, P2[i]); sP[ch][dl][2*i] = __uint_as_float(lo); sP[ch][dl][2*i+1] = __uint_as_float(hi);
    }
    __syncthreads();

    if (t < 128) {
        int pdl = t >> 4, pn = t & 15;
        float hrun = 0.f;
        #pragma unroll 4
        for (int c2 = 0; c2 < NCH; c2++) {
            float p = sP[c2][pdl][pn];
            float s = sS[c2][pdl][pn];
            sP[c2][pdl][pn] = hrun;
            hrun = fmaf(p, hrun, s);
        }
    }
    __syncthreads();

    #pragma unroll
    for (int i = 0; i < 8; i++)
        PK2(h2[i], __float_as_uint(sP[ch][dl][2*i]), __float_as_uint(sP[ch][dl][2*i+1]));

    for (int s = 0; s < CS; s++) {
        size_t m = mbase + s;
        float dt = g_dt[m * DQ + d];
        float xc = __bfloat162float(g_xcb[m * DQ + d]);
        u64t dt2 = bcast2(dt);
        u64t u2  = bcast2(dt * xc);
        const u64t* bp = (const u64t*)(g_bc + m * 32);
        u64t y2 = Z;
        #pragma unroll
        for (int i = 0; i < 8; i++) {
            u64t t2; F2_MUL(t2, dt2, Av2[i]);
            u64t dA2 = exp2x2(t2, MAG, NMAG, NEG1, PC4, PC3, PC2, PC1, ONE2);
            u64t uB2; F2_MUL(uB2, u2, bp[i]);
            F2_FMA(h2[i], dA2, h2[i], uB2);
            F2_FMA(y2, h2[i], bp[8 + i], y2);
        }
        uint32_t ylo, yhi; UPK2(ylo, yhi, y2);
        float y = __uint_as_float(ylo) + __uint_as_float(yhi);
        float z  = __bfloat162float(g_zb[m * DQ + d]);
        float sz = z / (1.f + __expf(-z));
        g_yb[m * DQ + d] = __float2bfloat16((y + Dv * xc) * sz);
    }
}

// ---------------- static init --------------------------------------------------
static struct SInit {
    SInit() {
        cudaFuncSetAttribute(mma_gemm<0,768>, cudaFuncAttributeMaxDynamicSharedMemorySize, NSTAGE*STAGEB);
        cudaFuncSetAttribute(mma_gemm<1,64>,  cudaFuncAttributeMaxDynamicSharedMemorySize, NSTAGE*STAGEB);
        cudaFuncSetAttribute(mma_gemm<2,768>, cudaFuncAttributeMaxDynamicSharedMemorySize, NSTAGE*STAGEB);
        cudaFuncSetAttribute(mma_gemm<3,768>, cudaFuncAttributeMaxDynamicSharedMemorySize, NSTAGE*STAGEB);
    }
} s_init;

// ---------------- PDL launch helper --------------------------------------------
template<typename F, typename... Args>
static inline void launchPDL(F k, dim3 g, dim3 b, size_t smem, Args... args)
{
    cudaLaunchConfig_t cfg = {};
    cfg.gridDim = g; cfg.blockDim = b;
    cfg.dynamicSmemBytes = smem; cfg.stream = 0;
    cudaLaunchAttribute attr[1];
    attr[0].id = cudaLaunchAttributeProgrammaticStreamSerialization;
    attr[0].val.programmaticStreamSerializationAllowed = 1;
    cfg.attrs = attr; cfg.numAttrs = 1;
    cudaLaunchKernelEx(&cfg, k, args...);
}

// ---------------- launch --------------------------------------------------------
extern "C" void kernel_launch(void* const* d_in, const int* in_sizes, int n_in,
                              void* d_out, int out_size)
{
    (void)in_sizes; (void)n_in; (void)out_size;
    const float* x          = (const float*)d_in[0];
    const float* norm_w     = (const float*)d_in[3];
    const float* in_proj_w  = (const float*)d_in[4];
    const float* in_proj_b  = (const float*)d_in[5];
    const float* conv_w     = (const float*)d_in[6];
    const float* conv_b     = (const float*)d_in[7];
    const float* x_proj_w   = (const float*)d_in[8];
    const float* dt_proj_w  = (const float*)d_in[9];
    const float* dt_proj_b  = (const float*)d_in[10];
    const float* A_log      = (const float*)d_in[11];
    const float* D_param    = (const float*)d_in[12];
    const float* out_proj_w = (const float*)d_in[13];
    const float* out_proj_b = (const float*)d_in[14];

    __nv_bfloat16* p_hidb; cudaGetSymbolAddress((void**)&p_hidb, g_hidb);
    __nv_bfloat16* p_xcb;  cudaGetSymbolAddress((void**)&p_xcb,  g_xcb);
    __nv_bfloat16* p_tmpb; cudaGetSymbolAddress((void**)&p_tmpb, g_tmpb);
    float* p_dt;   cudaGetSymbolAddress((void**)&p_dt,   g_dt);
    float* p_bc;   cudaGetSymbolAddress((void**)&p_bc,   g_bc);
    __nv_bfloat16* p_yb;   cudaGetSymbolAddress((void**)&p_yb,   g_yb);
    __nv_bfloat16* p_wib;  cudaGetSymbolAddress((void**)&p_wib,  g_wib);
    __nv_bfloat16* p_wob;  cudaGetSymbolAddress((void**)&p_wob,  g_wob);
    __nv_bfloat16* p_xpwb; cudaGetSymbolAddress((void**)&p_xpwb, g_xpwb);
    __nv_bfloat16* p_dtwb; cudaGetSymbolAddress((void**)&p_dtwb, g_dtwb);

    // 1: merged prep
    launchPDL(k_prep, dim3(1184), dim3(256), 0,
              in_proj_w, out_proj_w, x_proj_w, dt_proj_w,
              p_wib, p_wob, p_xpwb, p_dtwb);

    // 2: prenorm
    launchPDL(k_prenorm, dim3(MROWS), dim3(256), 0, x, norm_w);

    // 3: in_proj -> x bf16 | z bf16
    launchPDL(mma_gemm<0,768>, dim3(2*DQ/128, MROWS/128), dim3(256),
              (size_t)(NSTAGE*STAGEB),
              (const __nv_bfloat16*)p_hidb, (const __nv_bfloat16*)p_wib,
              in_proj_b, (const float*)nullptr,
              (float*)nullptr, (float*)nullptr, 2*DQ, 2*DQ);

    // 4: conv (profiled slot)
    launchPDL(k_conv, dim3(((MROWS/4)*(DQ/4) + 255)/256), dim3(256), 0,
              conv_w, conv_b);

    // 5: x_proj
    launchPDL(mma_gemm<3,768>, dim3(1, MROWS/128), dim3(256),
              (size_t)(NSTAGE*STAGEB),
              (const __nv_bfloat16*)p_xcb, (const __nv_bfloat16*)p_xpwb,
              (const float*)nullptr, (const float*)nullptr,
              (float*)nullptr, p_bc, 80, 80);

    // 6: dt projection + softplus
    launchPDL(mma_gemm<1,64>, dim3(6, MROWS/128), dim3(256),
              (size_t)(NSTAGE*STAGEB),
              (const __nv_bfloat16*)p_tmpb, (const __nv_bfloat16*)p_dtwb,
              dt_proj_b, (const float*)nullptr,
              p_dt, (float*)nullptr, DQ, DQ);

    // 7: fused scan
    launchPDL(k_scan, dim3(BQ*(DQ/8)), dim3(256), 0, A_log, D_param);

    // 8: out_proj + bias + x + pos
    launchPDL(mma_gemm<2,768>, dim3(DQ/128, MROWS/128), dim3(256),
              (size_t)(NSTAGE*STAGEB),
              (const __nv_bfloat16*)p_yb, (const __nv_bfloat16*)p_wob,
              out_proj_b, x, (float*)d_out, (float*)nullptr, DQ, DQ);
}

// round 14
// speedup vs baseline: 1.0806x; 1.0806x over previous
#include <cuda_runtime.h>
#include <cuda_bf16.h>
#include <cstdint>
#include <math.h>

#define BQ 8
#define LQ 1024
#define DQ 768
#define NST 16
#define RQ 48
#define MROWS (BQ*LQ)   // 8192
#define NCH 32
#define CS  (LQ/NCH)    // 32

// ---------------- scratch (device globals) ------------------------------------
__device__ __nv_bfloat16  g_hidb[MROWS*DQ];
__device__ __nv_bfloat16  g_xinb[MROWS*DQ];       // in_proj x-half, bf16
__device__ __nv_bfloat16  g_zb  [MROWS*DQ];       // in_proj z-half, bf16
__device__ __nv_bfloat16  g_xcb [MROWS*DQ];
__device__ __nv_bfloat16  g_tmpb[MROWS*64];       // dt_raw padded to 64, bf16
__device__ float          g_dt  [MROWS*DQ];
__device__ float          g_bc  [MROWS*32];
__device__ __nv_bfloat16  g_yb  [MROWS*DQ];
__device__ __nv_bfloat16  g_wib [2*DQ*DQ];
__device__ __nv_bfloat16  g_wob [DQ*DQ];
__device__ __nv_bfloat16  g_xpwb[80*DQ];
__device__ __nv_bfloat16  g_dtwb[DQ*64];
__device__ float          g_pos [LQ*DQ];

// ---------------- asm helpers -------------------------------------------------
__device__ __forceinline__ uint32_t smem_u32(const void* p) {
    uint32_t a;
    asm("{ .reg .u64 t; cvta.to.shared.u64 t, %1; cvt.u32.u64 %0, t; }" : "=r"(a) : "l"(p));
    return a;
}
#define CPASYNC16(d, s) \
    asm volatile("cp.async.cg.shared.global [%0], [%1], 16;" :: "r"(d), "l"(s))
#define CP_COMMIT()  asm volatile("cp.async.commit_group;")
#define CP_WAIT1()   asm volatile("cp.async.wait_group 1;")
#define CP_WAIT0()   asm volatile("cp.async.wait_group 0;")
#define LDSM4(r0, r1, r2, r3, a) \
    asm volatile("ldmatrix.sync.aligned.m8n8.x4.shared.b16 {%0,%1,%2,%3}, [%4];" \
        : "=r"(r0), "=r"(r1), "=r"(r2), "=r"(r3) : "r"(a))
#define MMA16816(d, a, b) \
    asm volatile("mma.sync.aligned.m16n8k16.row.col.f32.bf16.bf16.f32 " \
        "{%0,%1,%2,%3}, {%4,%5,%6,%7}, {%8,%9}, {%0,%1,%2,%3};" \
        : "+f"((d)[0]), "+f"((d)[1]), "+f"((d)[2]), "+f"((d)[3]) \
        : "r"((a)[0]), "r"((a)[1]), "r"((a)[2]), "r"((a)[3]), \
          "r"((b)[0]), "r"((b)[1]))

// ---- packed f32x2 ----
typedef unsigned long long u64t;
#define F2_FMA(d, a, b, c) asm("fma.rn.f32x2 %0, %1, %2, %3;" : "=l"(d) : "l"(a), "l"(b), "l"(c))
#define F2_MUL(d, a, b)    asm("mul.rn.f32x2 %0, %1, %2;"     : "=l"(d) : "l"(a), "l"(b))
#define F2_ADD(d, a, b)    asm("add.rn.f32x2 %0, %1, %2;"     : "=l"(d) : "l"(a), "l"(b))
#define PK2(d, lo, hi)     asm("mov.b64 %0, {%1, %2};" : "=l"(d) : "r"(lo), "r"(hi))
#define UPK2(lo, hi, s)    asm("mov.b64 {%0, %1}, %2;" : "=r"(lo), "=r"(hi) : "l"(s))

__device__ __forceinline__ u64t bcast2(float x) {
    uint32_t b = __float_as_uint(x);
    u64t d; PK2(d, b, b); return d;
}
__device__ __forceinline__ u64t exp2x2(u64t t2, u64t MAG, u64t NMAG, u64t NEG1,
                                       u64t C4, u64t C3, u64t C2, u64t C1, u64t ONE) {
    u64t z2; F2_ADD(z2, t2, MAG);
    uint32_t zl, zh; UPK2(zl, zh, z2);
    u64t zr2; F2_ADD(zr2, z2, NMAG);
    u64t f2;  F2_FMA(f2, zr2, NEG1, t2);
    u64t p2 = C4;
    F2_FMA(p2, p2, f2, C3);
    F2_FMA(p2, p2, f2, C2);
    F2_FMA(p2, p2, f2, C1);
    F2_FMA(p2, p2, f2, ONE);
    uint32_t pl, ph; UPK2(pl, ph, p2);
    pl += (zl - 0x4B400000u) << 23;
    ph += (zh - 0x4B400000u) << 23;
    u64t r; PK2(r, pl, ph); return r;
}
#define EXP2_CONSTS                                   \
    const u64t MAG  = bcast2(12582912.0f);            \
    const u64t NMAG = bcast2(-12582912.0f);           \
    const u64t NEG1 = bcast2(-1.0f);                  \
    const u64t PC4  = bcast2(9.6181291e-3f);          \
    const u64t PC3  = bcast2(5.5504110e-2f);          \
    const u64t PC2  = bcast2(2.4022651e-1f);          \
    const u64t PC1  = bcast2(6.9314718e-1f);          \
    const u64t ONE2 = bcast2(1.0f);

// ---------------- HMMA GEMM ----------------------------------------------------
// MODE 0: in_proj split: c<768 -> g_xinb bf16; c>=768 -> g_zb bf16
// MODE 1: C = softplus(acc + bias)
// MODE 2: C = acc + bias + x + pos-table
// MODE 3: x_proj split: c<48 -> tmpb; 48<=c<64 -> tmpb=0 & bc; 64<=c<80 -> bc
//         (launched with gridDim.y = 2*M/128; blockIdx.y covers 64-row halves
//          via m0 = blockIdx.y * 64 pattern handled by caller passing grid)
#define SROW 72
#define STGB (128*SROW*2)
#define STAGEB (2*STGB)
#define NSTAGE 3

template<int MODE, int KT>
__global__ void __launch_bounds__(256, 2) mma_gemm(
    const __nv_bfloat16* __restrict__ A, const __nv_bfloat16* __restrict__ W,
    const float* __restrict__ bias, const float* __restrict__ resid,
    float* __restrict__ C, float* __restrict__ bc, int N, int Wrows)
{
    extern __shared__ __align__(16) char dyn[];
    const uint32_t smemBase = smem_u32(dyn);

    const int tid  = threadIdx.x;
    const int lane = tid & 31;
    const int w    = tid >> 5;
    const int wm   = (w >> 2) * 64;
    const int wn   = (w & 3) * 32;
    const int gid  = lane >> 2;
    const int tig  = lane & 3;
    const int m0   = blockIdx.y * 128;
    const int n0   = blockIdx.x * 128;

    const uint32_t aOff = (uint32_t)(wm + (lane & 15)) * 144 + ((lane >> 4) << 4);
    const uint32_t bOff = (uint32_t)(wn + ((lane >> 4) << 3) + (lane & 7)) * 144
                        + (((lane >> 3) & 1) << 4) + STGB;

    auto issue = [&](int kt, int stage) {
        uint32_t dA = smemBase + stage * STAGEB;
        uint32_t dB = dA + STGB;
        int koff = kt * 64;
        #pragma unroll
        for (int i = 0; i < 4; i++) {
            int c = tid + i * 256;
            int row = c >> 3, q = c & 7;
            CPASYNC16(dA + row * 144 + q * 16,
                      A + (size_t)(m0 + row) * KT + koff + q * 8);
            int gn = n0 + row;
            int gnc = gn < Wrows ? gn : 0;
            CPASYNC16(dB + row * 144 + q * 16,
                      W + (size_t)gnc * KT + koff + q * 8);
        }
        CP_COMMIT();
    };

    float acc[4][4][4];
    #pragma unroll
    for (int mt = 0; mt < 4; mt++)
        #pragma unroll
        for (int nt = 0; nt < 4; nt++)
            #pragma unroll
            for (int i = 0; i < 4; i++) acc[mt][nt][i] = 0.f;

    constexpr int nk = KT / 64;
    issue(0, 0);
    if constexpr (nk > 1) issue(1, 1);

    #pragma unroll
    for (int kt = 0; kt < nk; kt++) {
        if (kt == nk - 1) CP_WAIT0();
        else              CP_WAIT1();
        __syncthreads();
        int st = kt % NSTAGE;
        uint32_t aB = smemBase + st * STAGEB + aOff;
        uint32_t bB = smemBase + st * STAGEB + bOff;
        #pragma unroll
        for (int ks = 0; ks < 4; ks++) {
            uint32_t ko = ks * 32;
            uint32_t af[4][4], bf[4][2];
            #pragma unroll
            for (int mt = 0; mt < 4; mt++)
                LDSM4(af[mt][0], af[mt][1], af[mt][2], af[mt][3],
                      aB + mt * (16 * 144) + ko);
            #pragma unroll
            for (int p = 0; p < 2; p++)
                LDSM4(bf[2*p][0], bf[2*p][1], bf[2*p+1][0], bf[2*p+1][1],
                      bB + p * (16 * 144) + ko);
            #pragma unroll
            for (int mt = 0; mt < 4; mt++)
                #pragma unroll
                for (int nt = 0; nt < 4; nt++)
                    MMA16816(acc[mt][nt], af[mt], bf[nt]);
        }
        if (kt + 2 < nk) issue(kt + 2, (kt + 2) % NSTAGE);
    }

    #pragma unroll
    for (int mt = 0; mt < 4; mt++) {
        int r0 = m0 + wm + mt * 16 + gid;
        #pragma unroll
        for (int nt = 0; nt < 4; nt++) {
            int c0 = n0 + wn + nt * 8 + tig * 2;
            if (MODE == 0) {
                float bv0 = bias[c0], bv1 = bias[c0 + 1];
                #pragma unroll
                for (int h = 0; h < 2; h++) {
                    int r = r0 + h * 8;
                    float v0 = acc[mt][nt][h * 2 + 0] + bv0;
                    float v1 = acc[mt][nt][h * 2 + 1] + bv1;
                    __nv_bfloat162 pv(__float2bfloat16(v0), __float2bfloat16(v1));
                    if (c0 < DQ)
                        *(__nv_bfloat162*)(g_xinb + (size_t)r * DQ + c0) = pv;
                    else
                        *(__nv_bfloat162*)(g_zb + (size_t)r * DQ + (c0 - DQ)) = pv;
                }
            } else if (MODE == 1) {
                #pragma unroll
                for (int h = 0; h < 2; h++) {
                    int r = r0 + h * 8;
                    #pragma unroll
                    for (int j = 0; j < 2; j++) {
                        int c = c0 + j;
                        float t = acc[mt][nt][h * 2 + j] + bias[c];
                        C[(size_t)r * DQ + c] =
                            fmaxf(t, 0.f) + log1pf(expf(-fabsf(t)));
                    }
                }
            } else if (MODE == 2) {
                #pragma unroll
                for (int h = 0; h < 2; h++) {
                    int r = r0 + h * 8;
                    int l = r & (LQ - 1);
                    float2 ps = *(const float2*)(g_pos + (size_t)l * DQ + c0);
                    float2 xr = *(const float2*)(resid + (size_t)r * DQ + c0);
                    float2 out;
                    out.x = acc[mt][nt][h * 2 + 0] + bias[c0]     + xr.x + ps.x;
                    out.y = acc[mt][nt][h * 2 + 1] + bias[c0 + 1] + xr.y + ps.y;
                    *(float2*)(C + (size_t)r * DQ + c0) = out;
                }
            } else {   // MODE 3
                #pragma unroll
                for (int h = 0; h < 2; h++) {
                    int r = r0 + h * 8;
                    #pragma unroll
                    for (int j = 0; j < 2; j++) {
                        int c = c0 + j;
                        float v = acc[mt][nt][h * 2 + j];
                        if (c < 48) {
                            g_tmpb[(size_t)r * 64 + c] = __float2bfloat16(v);
                        } else if (c < 64) {
                            g_tmpb[(size_t)r * 64 + c] = __float2bfloat16(0.f);
                            bc[(size_t)r * 32 + (c - 48)] = v;
                        } else if (c < 80) {
                            bc[(size_t)r * 32 + (c - 48)] = v;
                        }
                    }
                }
            }
        }
    }
}

// ---------------- merged prep: weights + dtw pad + pos table -------------------
__global__ void k_prep(const float* __restrict__ wi, const float* __restrict__ wo,
                       const float* __restrict__ xpw, const float* __restrict__ dtw,
                       __nv_bfloat16* __restrict__ di, __nv_bfloat16* __restrict__ dob,
                       __nv_bfloat16* __restrict__ xpb, __nv_bfloat16* __restrict__ dtb)
{
    const int n1q = (2*DQ*DQ) / 4;
    const int n2q = n1q + (DQ*DQ) / 4;
    const int n3q = n2q + (80*DQ) / 4;
    const int ndt = DQ * 64;
    const int npos = LQ * DQ;
    for (int i = blockIdx.x * blockDim.x + threadIdx.x; i < n3q + ndt + npos;
         i += gridDim.x * blockDim.x) {
        if (i < n3q) {
            const float* s; __nv_bfloat16* d; int q;
            if (i < n1q)      { s = wi;  d = di;  q = i; }
            else if (i < n2q) { s = wo;  d = dob; q = i - n1q; }
            else              { s = xpw; d = xpb; q = i - n2q; }
            float4 v = *(const float4*)(s + (size_t)q * 4);
            __nv_bfloat162* o = (__nv_bfloat162*)(d + (size_t)q * 4);
            o[0] = __nv_bfloat162(__float2bfloat16(v.x), __float2bfloat16(v.y));
            o[1] = __nv_bfloat162(__float2bfloat16(v.z), __float2bfloat16(v.w));
        } else if (i < n3q + ndt) {
            int idx = i - n3q;
            int n = idx >> 6, r = idx & 63;
            dtb[idx] = __float2bfloat16(r < RQ ? dtw[n * RQ + r] : 0.f);
        } else {
            int idx = i - n3q - ndt;
            int l = idx / DQ, c = idx % DQ;
            int chan = c >> 8, f = c & 255;
            float ch = (float)(l >> 6) * (1.0f/15.0f);
            float cw = (float)((l >> 2) & 15) * (1.0f/15.0f);
            float cd = (float)(l & 3) * (1.0f/3.0f);
            float cv = (chan == 0) ? ch : (chan == 1) ? cw : cd;
            float om  = exp2f(-(float)(f & 127) * (13.287712379549449f/128.0f));
            float arg = cv * om;
            g_pos[idx] = (f & 128) ? __cosf(arg) : __sinf(arg);
        }
    }
}

// ---------------- pos(table) + residual + rmsnorm ------------------------------
__global__ void __launch_bounds__(256) k_prenorm(const float* __restrict__ x,
                                                 const float* __restrict__ norm_w)
{
    int row = blockIdx.x;
    int l   = row & (LQ - 1);
    const float* xr = x + (size_t)row * DQ;
    const float* pr = g_pos + (size_t)l * DQ;
    float vals[3];
    float ss = 0.f;
    #pragma unroll
    for (int i = 0; i < 3; i++) {
        int j = threadIdx.x + i * 256;
        float v = xr[j] + pr[j];
        vals[i] = v;
        ss += v * v;
    }
    #pragma unroll
    for (int o = 16; o > 0; o >>= 1) ss += __shfl_xor_sync(0xffffffffu, ss, o);
    __shared__ float part[8];
    if ((threadIdx.x & 31) == 0) part[threadIdx.x >> 5] = ss;
    __syncthreads();
    float tot = part[0] + part[1] + part[2] + part[3]
              + part[4] + part[5] + part[6] + part[7];
    float scale = rsqrtf(tot * (1.0f/(float)DQ) + 1e-5f);

    __nv_bfloat16* hr = g_hidb + (size_t)row * DQ;
    #pragma unroll
    for (int i = 0; i < 3; i++) {
        int j = threadIdx.x + i * 256;
        hr[j] = __float2bfloat16(vals[i] * scale * norm_w[j]);
    }
}

// ---------------- causal conv (K=4, bf16 in) + silu ----------------------------
__device__ __forceinline__ float4 ld_bf4(const __nv_bfloat16* p) {
    uint2 u = *(const uint2*)p;
    __nv_bfloat162 a = *(const __nv_bfloat162*)&u.x;
    __nv_bfloat162 b = *(const __nv_bfloat162*)&u.y;
    return make_float4(__bfloat162float(a.x), __bfloat162float(a.y),
                       __bfloat162float(b.x), __bfloat162float(b.y));
}

__global__ void __launch_bounds__(256) k_conv(const float* __restrict__ conv_w,
                                              const float* __restrict__ conv_b)
{
    const int ND4 = DQ / 4;
    int idx = blockIdx.x * 256 + threadIdx.x;
    if (idx >= (MROWS/4) * ND4) return;
    int d4 = (idx % ND4) * 4;
    int m0 = (idx / ND4) * 4;
    int l0 = m0 & (LQ - 1);

    float4 w0 = *(const float4*)(conv_w + (d4+0)*4);
    float4 w1 = *(const float4*)(conv_w + (d4+1)*4);
    float4 w2 = *(const float4*)(conv_w + (d4+2)*4);
    float4 w3 = *(const float4*)(conv_w + (d4+3)*4);
    float4 bv = *(const float4*)(conv_b + d4);

    float4 xin[7];
    #pragma unroll
    for (int j = 0; j < 7; j++) {
        int lj = l0 - 3 + j;
        xin[j] = (lj >= 0)
               ? ld_bf4(g_xinb + (size_t)(m0 - 3 + j) * DQ + d4)
               : make_float4(0.f, 0.f, 0.f, 0.f);
    }
    #pragma unroll
    for (int t = 0; t < 4; t++) {
        float4 acc = bv;
        #pragma unroll
        for (int k = 0; k < 4; k++) {
            float4 xv = xin[t + k];
            acc.x = fmaf(xv.x, ((const float*)&w0)[k], acc.x);
            acc.y = fmaf(xv.y, ((const float*)&w1)[k], acc.y);
            acc.z = fmaf(xv.z, ((const float*)&w2)[k], acc.z);
            acc.w = fmaf(xv.w, ((const float*)&w3)[k], acc.w);
        }
        float4 s;
        s.x = acc.x / (1.f + __expf(-acc.x));
        s.y = acc.y / (1.f + __expf(-acc.y));
        s.z = acc.z / (1.f + __expf(-acc.z));
        s.w = acc.w / (1.f + __expf(-acc.w));
        __nv_bfloat162* o = (__nv_bfloat162*)(g_xcb + (size_t)(m0 + t) * DQ + d4);
        o[0] = __nv_bfloat162(__float2bfloat16(s.x), __float2bfloat16(s.y));
        o[1] = __nv_bfloat162(__float2bfloat16(s.z), __float2bfloat16(s.w));
    }
}

// ---------------- fused chunked scan -------------------------------------------
__global__ void __launch_bounds__(256) k_scan(const float* __restrict__ A_log,
                                              const float* __restrict__ D_param)
{
    __shared__ float sP[NCH][8][17];
    __shared__ float sS[NCH][8][17];

    int b  = blockIdx.x / (DQ/8);
    int d0 = (blockIdx.x % (DQ/8)) * 8;
    int t  = threadIdx.x;
    int ch = t >> 3;
    int dl = t & 7;
    int d  = d0 + dl;

    EXP2_CONSTS;
    u64t Av2[8];
    #pragma unroll
    for (int i = 0; i < 8; i++) {
        float a0 = -expf(A_log[d * NST + 2*i])     * 1.4426950408889634f;
        float a1 = -expf(A_log[d * NST + 2*i + 1]) * 1.4426950408889634f;
        PK2(Av2[i], __float_as_uint(a0), __float_as_uint(a1));
    }
    float Dv = D_param[d];

    u64t h2[8], P2[8];
    const u64t Z = bcast2(0.0f);
    #pragma unroll
    for (int i = 0; i < 8; i++) { h2[i] = Z; P2[i] = ONE2; }

    size_t mbase = (size_t)b * LQ + ch * CS;
    for (int s = 0; s < CS; s++) {
        size_t m = mbase + s;
        float dt = g_dt[m * DQ + d];
        float xc = __bfloat162float(g_xcb[m * DQ + d]);
        u64t dt2 = bcast2(dt);
        u64t u2  = bcast2(dt * xc);
        const u64t* bp = (const u64t*)(g_bc + m * 32);
        #pragma unroll
        for (int i = 0; i < 8; i++) {
            u64t t2; F2_MUL(t2, dt2, Av2[i]);
            u64t dA2 = exp2x2(t2, MAG, NMAG, NEG1, PC4, PC3, PC2, PC1, ONE2);
            u64t uB2; F2_MUL(uB2, u2, bp[i]);
            F2_FMA(h2[i], dA2, h2[i], uB2);
            F2_MUL(P2[i], P2[i], dA2);
        }
    }
    #pragma unroll
    for (int i = 0; i < 8; i++) {
        uint32_t lo, hi;
        UPK2(lo, hi, h2[i]); sS[ch][dl][2*i] = __uint_as_float(lo); sS[ch][dl][2*i+1] = __uint_as_float(hi);
        UPK2(lo, hi, P2[i]); sP[ch][dl][2*i] = __uint_as_float(lo); sP[ch][dl][2*i+1] = __uint_as_float(hi);
    }
    __syncthreads();

    if (t < 128) {
        int pdl = t >> 4, pn = t & 15;
        float hrun = 0.f;
        #pragma unroll 4
        for (int c2 = 0; c2 < NCH; c2++) {
            float p = sP[c2][pdl][pn];
            float s = sS[c2][pdl][pn];
            sP[c2][pdl][pn] = hrun;
            hrun = fmaf(p, hrun, s);
        }
    }
    __syncthreads();

    #pragma unroll
    for (int i = 0; i < 8; i++)
        PK2(h2[i], __float_as_uint(sP[ch][dl][2*i]), __float_as_uint(sP[ch][dl][2*i+1]));

    for (int s = 0; s < CS; s++) {
        size_t m = mbase + s;
        float dt = g_dt[m * DQ + d];
        float xc = __bfloat162float(g_xcb[m * DQ + d]);
        u64t dt2 = bcast2(dt);
        u64t u2  = bcast2(dt * xc);
        const u64t* bp = (const u64t*)(g_bc + m * 32);
        u64t y2 = Z;
        #pragma unroll
        for (int i = 0; i < 8; i++) {
            u64t t2; F2_MUL(t2, dt2, Av2[i]);
            u64t dA2 = exp2x2(t2, MAG, NMAG, NEG1, PC4, PC3, PC2, PC1, ONE2);
            u64t uB2; F2_MUL(uB2, u2, bp[i]);
            F2_FMA(h2[i], dA2, h2[i], uB2);
            F2_FMA(y2, h2[i], bp[8 + i], y2);
        }
        uint32_t ylo, yhi; UPK2(ylo, yhi, y2);
        float y = __uint_as_float(ylo) + __uint_as_float(yhi);
        float z  = __bfloat162float(g_zb[m * DQ + d]);
        float sz = z / (1.f + __expf(-z));
        g_yb[m * DQ + d] = __float2bfloat16((y + Dv * xc) * sz);
    }
}

// ---------------- static init --------------------------------------------------
static struct SInit {
    SInit() {
        cudaFuncSetAttribute(mma_gemm<0,768>, cudaFuncAttributeMaxDynamicSharedMemorySize, NSTAGE*STAGEB);
        cudaFuncSetAttribute(mma_gemm<1,64>,  cudaFuncAttributeMaxDynamicSharedMemorySize, NSTAGE*STAGEB);
        cudaFuncSetAttribute(mma_gemm<2,768>, cudaFuncAttributeMaxDynamicSharedMemorySize, NSTAGE*STAGEB);
        cudaFuncSetAttribute(mma_gemm<3,768>, cudaFuncAttributeMaxDynamicSharedMemorySize, NSTAGE*STAGEB);
    }
} s_init;

// ---------------- launch --------------------------------------------------------
extern "C" void kernel_launch(void* const* d_in, const int* in_sizes, int n_in,
                              void* d_out, int out_size)
{
    (void)in_sizes; (void)n_in; (void)out_size;
    const float* x          = (const float*)d_in[0];
    const float* norm_w     = (const float*)d_in[3];
    const float* in_proj_w  = (const float*)d_in[4];
    const float* in_proj_b  = (const float*)d_in[5];
    const float* conv_w     = (const float*)d_in[6];
    const float* conv_b     = (const float*)d_in[7];
    const float* x_proj_w   = (const float*)d_in[8];
    const float* dt_proj_w  = (const float*)d_in[9];
    const float* dt_proj_b  = (const float*)d_in[10];
    const float* A_log      = (const float*)d_in[11];
    const float* D_param    = (const float*)d_in[12];
    const float* out_proj_w = (const float*)d_in[13];
    const float* out_proj_b = (const float*)d_in[14];

    __nv_bfloat16* p_hidb; cudaGetSymbolAddress((void**)&p_hidb, g_hidb);
    __nv_bfloat16* p_xcb;  cudaGetSymbolAddress((void**)&p_xcb,  g_xcb);
    __nv_bfloat16* p_tmpb; cudaGetSymbolAddress((void**)&p_tmpb, g_tmpb);
    float* p_dt;   cudaGetSymbolAddress((void**)&p_dt,   g_dt);
    float* p_bc;   cudaGetSymbolAddress((void**)&p_bc,   g_bc);
    __nv_bfloat16* p_yb;   cudaGetSymbolAddress((void**)&p_yb,   g_yb);
    __nv_bfloat16* p_wib;  cudaGetSymbolAddress((void**)&p_wib,  g_wib);
    __nv_bfloat16* p_wob;  cudaGetSymbolAddress((void**)&p_wob,  g_wob);
    __nv_bfloat16* p_xpwb; cudaGetSymbolAddress((void**)&p_xpwb, g_xpwb);
    __nv_bfloat16* p_dtwb; cudaGetSymbolAddress((void**)&p_dtwb, g_dtwb);

    // 1: merged prep
    k_prep<<<1184, 256>>>(in_proj_w, out_proj_w, x_proj_w, dt_proj_w,
                          p_wib, p_wob, p_xpwb, p_dtwb);

    // 2: prenorm
    k_prenorm<<<MROWS, 256>>>(x, norm_w);

    // 3: in_proj -> x bf16 | z bf16
    mma_gemm<0,768><<<dim3(2*DQ/128, MROWS/128), 256, NSTAGE*STAGEB>>>(
        p_hidb, p_wib, in_proj_b, nullptr, nullptr, nullptr, 2*DQ, 2*DQ);

    // 4: conv (profiled slot)
    k_conv<<<((MROWS/4)*(DQ/4) + 255)/256, 256>>>(conv_w, conv_b);

    // 5: x_proj
    mma_gemm<3,768><<<dim3(1, MROWS/128), 256, NSTAGE*STAGEB>>>(
        p_xcb, p_xpwb, nullptr, nullptr, nullptr, p_bc, 80, 80);

    // 6: dt projection + softplus
    mma_gemm<1,64><<<dim3(6, MROWS/128), 256, NSTAGE*STAGEB>>>(
        p_tmpb, p_dtwb, dt_proj_b, nullptr, p_dt, nullptr, DQ, DQ);

    // 7: fused scan
    k_scan<<<BQ*(DQ/8), 256>>>(A_log, D_param);

    // 8: out_proj + bias + x + pos
    mma_gemm<2,768><<<dim3(DQ/128, MROWS/128), 256, NSTAGE*STAGEB>>>(
        p_yb, p_wob, out_proj_b, x, (float*)d_out, nullptr, DQ, DQ);
}